// round 9
// baseline (speedup 1.0000x reference)
#include <cuda_runtime.h>
#include <cuda_bf16.h>
#include <math_constants.h>

// SupPixPool: out[b][c][k] = max over pixels p with spx[b][p]==k of img[b][c][p]
// B=4, C=64, H=W=512 (HW=262144), K=1024.
//
// R7: conflict-free sub-slot scatter. R2/R4/R6 established the binding
// resource is the smem crossbar under random bank conflicts (~3.6 RMW
// lanes/cyc/SM, occupancy-invariant). Fix: 32 sub-slots per segment,
// slot = k*32 + lane -> bank == lane -> every ATOMS is conflict-free.
// Merge 32 sub-slots per segment with one conflict-free warp LDS +
// __reduce_max_sync (REDUX, ALU pipe), then global atomicMax into d_out.
// Bias +128.0f keeps the single-int-atomicMax encoding. Last block per
// (b, cgroup) decodes (subtract bias) via ticket counter.

#define HW    (512 * 512)
#define KSEG  1024
#define CTOT  64
#define BTOT  4
#define RSUB  32                  // sub-slots per segment (== warp lanes)
#define CSEQ  2                   // channels per block, processed sequentially
#define NCG   (CTOT / CSEQ)       // 32 channel-groups
#define RANGES 2                  // pixel-range splits per (b, cgroup)
#define PPB   (HW / RANGES)       // 131072 pixels per block per channel
#define NTHR  512
#define PPT   (PPB / NTHR)        // 256 pixels per thread per channel
#define BIAS  128.0f
#define NEG_INF_BITS 0xFF800000u
#define SLOT_BYTES (KSEG * RSUB * 4)   // 128 KB dynamic smem

__device__ int g_tickets[BTOT * NCG];   // zeroed by init kernel

__global__ void __launch_bounds__(256) sp_init_kernel(uint4* __restrict__ out) {
    const uint4 v = make_uint4(NEG_INF_BITS, NEG_INF_BITS, NEG_INF_BITS, NEG_INF_BITS);
    out[blockIdx.x * 256 + threadIdx.x] = v;   // 256 blocks x 256 thr x 16B = 1MB
    if (blockIdx.x == 0 && threadIdx.x < BTOT * NCG)
        g_tickets[threadIdx.x] = 0;
}

__global__ void __launch_bounds__(NTHR) sp_main_kernel(const float* __restrict__ img,
                                                       const int*   __restrict__ spx,
                                                       int*         __restrict__ out) {
    extern __shared__ int slots[];          // [KSEG * RSUB] = 128 KB
    __shared__ int staging[KSEG];           // 4 KB
    __shared__ int is_last;

    const int tid  = threadIdx.x;
    const int lane = tid & 31;
    const int wid  = tid >> 5;              // 0..15

    const int range = blockIdx.x;           // 0..RANGES-1
    const int cg    = blockIdx.y;           // 0..NCG-1
    const int b     = blockIdx.z;           // 0..BTOT-1

    // Init all sub-slots to -inf (phase resets are folded into the merge).
    {
        const uint4 v = make_uint4(NEG_INF_BITS, NEG_INF_BITS, NEG_INF_BITS, NEG_INF_BITS);
        uint4* s4p = reinterpret_cast<uint4*>(slots);
        #pragma unroll
        for (int i = tid; i < KSEG * RSUB / 4; i += NTHR)
            s4p[i] = v;
    }
    __syncthreads();

    const int* spxp = spx + b * HW + range * PPB;
    int* laneslot = slots + lane;           // addr = laneslot + k*32 -> bank == lane

    for (int phase = 0; phase < CSEQ; ++phase) {
        const int c = cg * CSEQ + phase;
        const float* imgp = img + ((size_t)(b * CTOT + c)) * HW + range * PPB;

        // Scatter: 256 pixels/thread, conflict-free ATOMS.
        #pragma unroll 4
        for (int i = 0; i < PPT / 4; ++i) {
            const int idx = (i * NTHR + tid) * 4;
            const int4   s = __ldg(reinterpret_cast<const int4*>(spxp + idx));
            const float4 v = __ldcs(reinterpret_cast<const float4*>(imgp + idx));
            atomicMax(laneslot + s.x * RSUB, __float_as_int(v.x + BIAS));
            atomicMax(laneslot + s.y * RSUB, __float_as_int(v.y + BIAS));
            atomicMax(laneslot + s.z * RSUB, __float_as_int(v.z + BIAS));
            atomicMax(laneslot + s.w * RSUB, __float_as_int(v.w + BIAS));
        }
        __syncthreads();

        // Merge: warp-wide conflict-free read of a segment's 32 sub-slots,
        // REDUX max, reset slots for next phase, stage result.
        #pragma unroll 4
        for (int i = 0; i < KSEG / 16; ++i) {
            const int k = wid * (KSEG / 16) + i;
            const int v = slots[k * RSUB + lane];
            slots[k * RSUB + lane] = (int)NEG_INF_BITS;
            const int m = __reduce_max_sync(0xFFFFFFFFu, v);
            if (lane == 0) staging[k] = m;
        }
        __syncthreads();

        // Global merge for this channel.
        int* outg = out + (b * CTOT + c) * KSEG;
        atomicMax(&outg[tid], staging[tid]);
        atomicMax(&outg[tid + NTHR], staging[tid + NTHR]);
        __syncthreads();
    }

    // Last of the RANGES blocks for this (b, cg) decodes both channels.
    __threadfence();
    if (tid == 0)
        is_last = (atomicAdd(&g_tickets[b * NCG + cg], 1) == RANGES - 1);
    __syncthreads();

    if (is_last) {
        int* outg = out + (b * CTOT + cg * CSEQ) * KSEG;   // CSEQ*KSEG = 2048 entries
        float* outf = reinterpret_cast<float*>(outg);
        #pragma unroll
        for (int i = tid * 4; i < CSEQ * KSEG; i += NTHR * 4) {
            int4 w = __ldcg(reinterpret_cast<const int4*>(outg + i));
            float4 f;
            f.x = __int_as_float(w.x) - BIAS;
            f.y = __int_as_float(w.y) - BIAS;
            f.z = __int_as_float(w.z) - BIAS;
            f.w = __int_as_float(w.w) - BIAS;
            *reinterpret_cast<float4*>(outf + i) = f;
        }
    }
}

extern "C" void kernel_launch(void* const* d_in, const int* in_sizes, int n_in,
                              void* d_out, int out_size) {
    const float* img = (const float*)d_in[0];   // [4, 64, 512, 512] f32
    const int*   spx = (const int*)d_in[1];     // [4, 512, 512] i32

    static int smem_set = 0;
    if (!smem_set) {
        cudaFuncSetAttribute(sp_main_kernel,
                             cudaFuncAttributeMaxDynamicSharedMemorySize, SLOT_BYTES);
        smem_set = 1;
    }

    sp_init_kernel<<<256, 256>>>((uint4*)d_out);

    dim3 grid(RANGES, NCG, BTOT);               // 2 x 32 x 4 = 256 blocks
    sp_main_kernel<<<grid, NTHR, SLOT_BYTES>>>(img, spx, (int*)d_out);
}

// round 10
// speedup vs baseline: 1.7413x; 1.7413x over previous
#include <cuda_runtime.h>
#include <cuda_bf16.h>
#include <math_constants.h>

// SupPixPool: out[b][c][k] = max over pixels p with spx[b][p]==k of img[b][c][p]
// B=4, C=64, H=W=512 (HW=262144), K=1024.
//
// R9: conflict-free sub-slot scatter (slot = k*32 + lane -> bank == lane,
// zero-conflict ATOMS) at FULL parallelism. R7 proved the layout relieves
// the smem crossbar (L1 55->29%) but starved at 16 warps / 1.73 waves.
// Now: one block per (batch, channel-pair), 1024 threads (32 warps),
// grid 128 = single wave. Each block sees ALL pixels for its channels, so
// the sub-slot merge is the FINAL result -> direct coalesced store. No init
// kernel, no global atomics, no tickets, no decode. One kernel total.
//
// Bias +128.0f: all values positive floats -> float order == s32 bit order
// -> single atomicMax(int) combine. Decode = subtract bias.

#define HW    (512 * 512)
#define KSEG  1024
#define CTOT  64
#define BTOT  4
#define RSUB  32                  // sub-slots per segment (== warp lanes)
#define CSEQ  2                   // channels per block, sequential phases
#define NCG   (CTOT / CSEQ)       // 32 channel-groups
#define NTHR  1024
#define NWARP (NTHR / 32)         // 32
#define PPT   (HW / NTHR)         // 256 pixels per thread per channel
#define BIAS  128.0f
#define NEG_INF_BITS 0xFF800000u
#define SLOT_BYTES (KSEG * RSUB * 4)   // 128 KB dynamic smem

__global__ void __launch_bounds__(NTHR) sp_main_kernel(const float* __restrict__ img,
                                                       const int*   __restrict__ spx,
                                                       float* __restrict__ out) {
    extern __shared__ int slots[];          // [KSEG * RSUB] = 128 KB

    const int tid  = threadIdx.x;
    const int lane = tid & 31;
    const int wid  = tid >> 5;              // 0..31

    const int cg = blockIdx.x;              // 0..NCG-1
    const int b  = blockIdx.y;              // 0..BTOT-1

    // Init all sub-slots to -inf.
    {
        const uint4 v = make_uint4(NEG_INF_BITS, NEG_INF_BITS, NEG_INF_BITS, NEG_INF_BITS);
        uint4* s4p = reinterpret_cast<uint4*>(slots);
        #pragma unroll
        for (int i = tid; i < KSEG * RSUB / 4; i += NTHR)
            s4p[i] = v;
    }
    __syncthreads();

    const int* spxp = spx + b * HW;
    int* laneslot = slots + lane;           // + k*32 -> bank == lane, conflict-free

    #pragma unroll
    for (int phase = 0; phase < CSEQ; ++phase) {
        const int c = cg * CSEQ + phase;
        const float* imgp = img + ((size_t)(b * CTOT + c)) * HW;

        // Scatter: 256 pixels/thread, zero-bank-conflict ATOMS.
        #pragma unroll 4
        for (int i = 0; i < PPT / 4; ++i) {
            const int idx = (i * NTHR + tid) * 4;
            const int4   s = __ldg(reinterpret_cast<const int4*>(spxp + idx));
            const float4 v = __ldcs(reinterpret_cast<const float4*>(imgp + idx));
            atomicMax(laneslot + s.x * RSUB, __float_as_int(v.x + BIAS));
            atomicMax(laneslot + s.y * RSUB, __float_as_int(v.y + BIAS));
            atomicMax(laneslot + s.z * RSUB, __float_as_int(v.z + BIAS));
            atomicMax(laneslot + s.w * RSUB, __float_as_int(v.w + BIAS));
        }
        __syncthreads();

        // Merge: warp w owns segments [w*32, w*32+32). Conflict-free LDS of
        // the 32 sub-slots, REDUX max, lane-select so lane i holds segment
        // w*32+i, then one coalesced 128B store of FINAL results.
        int keep = (int)NEG_INF_BITS;
        #pragma unroll
        for (int i = 0; i < 32; ++i) {
            const int k = wid * 32 + i;
            const int v = slots[k * RSUB + lane];
            if (phase + 1 < CSEQ)
                slots[k * RSUB + lane] = (int)NEG_INF_BITS;   // reset for next phase
            const int m = __reduce_max_sync(0xFFFFFFFFu, v);
            if (lane == i) keep = m;
        }
        out[(b * CTOT + c) * KSEG + wid * 32 + lane] = __int_as_float(keep) - BIAS;

        __syncthreads();   // resets visible before next phase's scatter
    }
}

extern "C" void kernel_launch(void* const* d_in, const int* in_sizes, int n_in,
                              void* d_out, int out_size) {
    const float* img = (const float*)d_in[0];   // [4, 64, 512, 512] f32
    const int*   spx = (const int*)d_in[1];     // [4, 512, 512] i32

    static int smem_set = 0;
    if (!smem_set) {
        cudaFuncSetAttribute(sp_main_kernel,
                             cudaFuncAttributeMaxDynamicSharedMemorySize, SLOT_BYTES);
        smem_set = 1;
    }

    dim3 grid(NCG, BTOT);                       // 32 x 4 = 128 blocks, single wave
    sp_main_kernel<<<grid, NTHR, SLOT_BYTES>>>(img, spx, (float*)d_out);
}

// round 11
// speedup vs baseline: 1.8926x; 1.0869x over previous
#include <cuda_runtime.h>
#include <cuda_bf16.h>
#include <math_constants.h>

// SupPixPool: out[b][c][k] = max over pixels p with spx[b][p]==k of img[b][c][p]
// B=4, C=64, H=W=512 (HW=262144), K=1024.
//
// R11: RSUB 32 -> 16 (64 KB slots) so 2 CTAs/SM co-reside -> occ 100%,
// grid 256 (one CTA per (b,c) channel, CSEQ=1), all 148 SMs active.
// R10 profile (occ 51%, nothing saturated, ATOMS at 4.7 lanes/cyc/SM vs
// >=16 ceiling) says latency-bound; doubling resident warps should beat
// the ~1.5x ATOMS bank-conflict cost of the narrower sub-slot layout.
// Still single-kernel: each CTA sees all pixels of its channel, so the
// sub-slot merge is final -> direct coalesced store. Bias +128.0f keeps
// the single-int-atomicMax encoding.

#define HW    (512 * 512)
#define KSEG  1024
#define CTOT  64
#define BTOT  4
#define RSUB  16                  // sub-slots per segment
#define NTHR  1024
#define PPT   (HW / NTHR)         // 256 pixels per thread
#define BIAS  128.0f
#define NEG_INF_BITS 0xFF800000u
#define SLOT_BYTES (KSEG * RSUB * 4)   // 64 KB dynamic smem

__global__ void __launch_bounds__(NTHR, 2) sp_main_kernel(const float* __restrict__ img,
                                                          const int*   __restrict__ spx,
                                                          float* __restrict__ out) {
    extern __shared__ int slots[];          // [KSEG * RSUB] = 64 KB

    const int tid  = threadIdx.x;
    const int lane = tid & 31;
    const int wid  = tid >> 5;              // 0..31
    const int sub  = lane & 15;

    const int c = blockIdx.x;               // 0..CTOT-1
    const int b = blockIdx.y;               // 0..BTOT-1

    // Init all sub-slots to -inf.
    {
        const uint4 v = make_uint4(NEG_INF_BITS, NEG_INF_BITS, NEG_INF_BITS, NEG_INF_BITS);
        uint4* s4p = reinterpret_cast<uint4*>(slots);
        #pragma unroll
        for (int i = tid; i < KSEG * RSUB / 4; i += NTHR)
            s4p[i] = v;
    }
    __syncthreads();

    const int*   spxp = spx + b * HW;
    const float* imgp = img + ((size_t)(b * CTOT + c)) * HW;
    int* laneslot = slots + sub;            // + k*16 -> ~1.5-way bank spread

    // Scatter: 256 pixels/thread, sub-slotted ATOMS.
    #pragma unroll 4
    for (int i = 0; i < PPT / 4; ++i) {
        const int idx = (i * NTHR + tid) * 4;
        const int4   s = __ldg(reinterpret_cast<const int4*>(spxp + idx));
        const float4 v = __ldcs(reinterpret_cast<const float4*>(imgp + idx));
        atomicMax(laneslot + s.x * RSUB, __float_as_int(v.x + BIAS));
        atomicMax(laneslot + s.y * RSUB, __float_as_int(v.y + BIAS));
        atomicMax(laneslot + s.z * RSUB, __float_as_int(v.z + BIAS));
        atomicMax(laneslot + s.w * RSUB, __float_as_int(v.w + BIAS));
    }
    __syncthreads();

    // Merge: warp w owns segments [w*32, w*32+32). Each iteration the lower
    // 16 lanes reduce segment wbase+i, the upper 16 lanes segment
    // wbase+16+i, via width-16 shfl butterflies. Lane keeps the result for
    // segment wbase+lane (sub == i) -> final store is fully coalesced.
    {
        const int wbase = wid * 32;
        const int hi    = lane >> 4;        // 0 = lower half, 1 = upper half
        int keep = (int)NEG_INF_BITS;
        #pragma unroll
        for (int i = 0; i < 16; ++i) {
            const int k = wbase + hi * 16 + i;
            int v = slots[k * RSUB + sub];
            #pragma unroll
            for (int m = 8; m >= 1; m >>= 1)
                v = max(v, __shfl_xor_sync(0xFFFFFFFFu, v, m, 16));
            if (sub == i) keep = v;
        }
        out[(b * CTOT + c) * KSEG + wbase + lane] = __int_as_float(keep) - BIAS;
    }
}

extern "C" void kernel_launch(void* const* d_in, const int* in_sizes, int n_in,
                              void* d_out, int out_size) {
    const float* img = (const float*)d_in[0];   // [4, 64, 512, 512] f32
    const int*   spx = (const int*)d_in[1];     // [4, 512, 512] i32

    static int smem_set = 0;
    if (!smem_set) {
        cudaFuncSetAttribute(sp_main_kernel,
                             cudaFuncAttributeMaxDynamicSharedMemorySize, SLOT_BYTES);
        smem_set = 1;
    }

    dim3 grid(CTOT, BTOT);                      // 64 x 4 = 256 blocks, 2 CTAs/SM
    sp_main_kernel<<<grid, NTHR, SLOT_BYTES>>>(img, spx, (float*)d_out);
}